// round 1
// baseline (speedup 1.0000x reference)
#include <cuda_runtime.h>
#include <cstdint>

#define Bq 32
#define Hh 32
#define KVH 8
#define Gq 4
#define Dd 128
#define BS 128
#define NB 448
#define SCALE 0.08838834764831845f

// Flash-decode partial scratch (static device globals: allocation-free).
__device__ float g_po[(size_t)NB * KVH * Gq * Dd];   // ~7.3 MB
__device__ float g_pm[NB * KVH * Gq];
__device__ float g_pl[NB * KVH * Gq];

// Packed f32x2 FMA (FFMA2) — 2 MACs per issue slot; only reachable via PTX.
__device__ __forceinline__ float2 ffma2(float2 a, float2 b, float2 c) {
    unsigned long long ua = *reinterpret_cast<unsigned long long*>(&a);
    unsigned long long ub = *reinterpret_cast<unsigned long long*>(&b);
    unsigned long long uc = *reinterpret_cast<unsigned long long*>(&c);
    unsigned long long ur;
    asm("fma.rn.f32x2 %0, %1, %2, %3;" : "=l"(ur) : "l"(ua), "l"(ub), "l"(uc));
    return *reinterpret_cast<float2*>(&ur);
}

__global__ __launch_bounds__(128, 4)
void attn_partial_kernel(
    const float* __restrict__ query,
    const float* __restrict__ knew,
    const float* __restrict__ vnew,
    const float* __restrict__ kcache,
    const float* __restrict__ vcache,
    const int*   __restrict__ block_list,
    const int*   __restrict__ block_groups,
    const float* __restrict__ block_bias,
    const int*   __restrict__ block_indices,
    const int*   __restrict__ block_offsets,
    const float* __restrict__ alibi_blocks,
    const float* __restrict__ slopes)
{
    // 33792 + 2048 + 2048 + 8192 + 512 + 32 + 8 = ~46.6 KB static smem
    __shared__ float Ks[64][132];          // half-tile of K, padded rows (conflict-free LDS.128)
    __shared__ float Qs[Gq][Dd];           // scaled Q for the 4 grouped heads
    __shared__ float Sv[Gq][BS];           // scores, then p
    __shared__ float Ored[4][Gq][Dd];      // per-warp PV partials
    __shared__ int   maskS[BS];
    __shared__ float sm_m[Gq], sm_l[Gq];
    __shared__ int   s_ins_slot, s_ins_b;

    const int n   = blockIdx.x;            // active block id
    const int kvh = blockIdx.y;            // kv head
    const int tid = threadIdx.x;           // 0..127 (token id for QK)
    const int w   = tid >> 5;              // warp 0..3
    const int ln  = tid & 31;

    const int b    = block_groups[n];
    const int cblk = block_list[n];

    // Does the new decode token land in this cache block? (reference inserts
    // k_new/v_new at (block_indices[b'], block_offsets[b']) before reading)
    if (tid == 0) {
        int islot = -1, ib = 0;
        for (int bi = 0; bi < Bq; bi++) {
            if (block_indices[bi] == cblk) { islot = block_offsets[bi]; ib = bi; }
        }
        s_ins_slot = islot;
        s_ins_b    = ib;
    }

    // Stage pre-scaled Q: 4 heads x 128 d
    {
        const int h  = w;
        const int d0 = ln * 4;
        float4 q4 = *reinterpret_cast<const float4*>(
            query + (size_t)b * Hh * Dd + (size_t)(kvh * Gq + h) * Dd + d0);
        q4.x *= SCALE; q4.y *= SCALE; q4.z *= SCALE; q4.w *= SCALE;
        *reinterpret_cast<float4*>(&Qs[h][d0]) = q4;
    }

    // Per-token bias / alibi / validity (skip masked slots entirely: exp==0)
    const float bb_t    = block_bias[n * BS + tid];
    const float ab_t    = alibi_blocks[n * BS + tid];
    const int   valid_t = bb_t > -1.0e8f;
    maskS[tid] = valid_t;
    __syncthreads();

    const int ins_slot = s_ins_slot;
    const int ins_b    = s_ins_b;

    // ---------------- QK: two 64-token halves through smem ----------------
    float2 accA[Gq], accB[Gq];
    #pragma unroll
    for (int h = 0; h < Gq; h++) {
        accA[h] = make_float2(0.f, 0.f);
        accB[h] = make_float2(0.f, 0.f);
    }

    #pragma unroll
    for (int hp = 0; hp < 2; hp++) {
        const int tbase = hp * 64;
        // cooperative stage: each warp-iter loads one full 512B K row (coalesced)
        #pragma unroll
        for (int j = 0; j < 16; j++) {
            const int i   = tid + j * 128;
            const int tok = i >> 5;
            const int c   = i & 31;
            const int tg  = tbase + tok;
            if (maskS[tg]) {
                const float* src =
                    (tg == ins_slot)
                      ? (knew + ((size_t)ins_b * KVH + kvh) * Dd + c * 4)
                      : (kcache + (((size_t)cblk * BS + tg) * KVH + kvh) * Dd + c * 4);
                *reinterpret_cast<float4*>(&Ks[tok][c * 4]) =
                    *reinterpret_cast<const float4*>(src);
            }
        }
        __syncthreads();
        // threads whose token falls in this half compute 4 dot products
        if ((tid >> 6) == hp && valid_t) {
            const int r = tid & 63;
            const float* krow = &Ks[r][0];
            #pragma unroll
            for (int c = 0; c < 32; c++) {
                const float4 k4 = *reinterpret_cast<const float4*>(krow + c * 4);
                const float2 klo = make_float2(k4.x, k4.y);
                const float2 khi = make_float2(k4.z, k4.w);
                #pragma unroll
                for (int h = 0; h < Gq; h++) {
                    const float4 q4 = *reinterpret_cast<const float4*>(&Qs[h][c * 4]);
                    accA[h] = ffma2(klo, make_float2(q4.x, q4.y), accA[h]);
                    accB[h] = ffma2(khi, make_float2(q4.z, q4.w), accB[h]);
                }
            }
        }
        __syncthreads();
    }

    // scores + alibi + bias
    float s[Gq];
    #pragma unroll
    for (int h = 0; h < Gq; h++) {
        if (valid_t) {
            const float slope = slopes[kvh * Gq + h];
            s[h] = accA[h].x + accA[h].y + accB[h].x + accB[h].y
                 + ab_t * slope + bb_t;
        } else {
            s[h] = -1.0e30f;
        }
        Sv[h][tid] = s[h];
    }
    __syncthreads();

    // per-head block max (warp w owns head w)
    {
        float v = fmaxf(fmaxf(Sv[w][ln], Sv[w][ln + 32]),
                        fmaxf(Sv[w][ln + 64], Sv[w][ln + 96]));
        #pragma unroll
        for (int off = 16; off > 0; off >>= 1)
            v = fmaxf(v, __shfl_xor_sync(0xffffffffu, v, off));
        if (ln == 0) sm_m[w] = v;
    }
    __syncthreads();

    // p = exp(s - m_block)
    #pragma unroll
    for (int h = 0; h < Gq; h++) {
        const float p = valid_t ? __expf(s[h] - sm_m[h]) : 0.f;
        Sv[h][tid] = p;
    }
    __syncthreads();

    // per-head block sum
    {
        float v = Sv[w][ln] + Sv[w][ln + 32] + Sv[w][ln + 64] + Sv[w][ln + 96];
        #pragma unroll
        for (int off = 16; off > 0; off >>= 1)
            v += __shfl_xor_sync(0xffffffffu, v, off);
        if (ln == 0) sm_l[w] = v;
    }

    // ---------------- PV: warp w -> 32 tokens, lane owns 4 d's ----------------
    float2 olo[Gq], ohi[Gq];
    #pragma unroll
    for (int h = 0; h < Gq; h++) {
        olo[h] = make_float2(0.f, 0.f);
        ohi[h] = make_float2(0.f, 0.f);
    }
    const int d0 = ln * 4;
    #pragma unroll 4
    for (int i = 0; i < 32; i++) {
        const int t = w * 32 + i;
        if (maskS[t]) {
            const float* vrow =
                (t == ins_slot)
                  ? (vnew + ((size_t)ins_b * KVH + kvh) * Dd)
                  : (vcache + (((size_t)cblk * BS + t) * KVH + kvh) * Dd);
            const float4 v4 = *reinterpret_cast<const float4*>(vrow + d0);
            const float2 vlo = make_float2(v4.x, v4.y);
            const float2 vhi = make_float2(v4.z, v4.w);
            #pragma unroll
            for (int h = 0; h < Gq; h++) {
                const float pb = Sv[h][t];
                const float2 pp = make_float2(pb, pb);
                olo[h] = ffma2(pp, vlo, olo[h]);
                ohi[h] = ffma2(pp, vhi, ohi[h]);
            }
        }
    }

    #pragma unroll
    for (int h = 0; h < Gq; h++) {
        const float4 ov = make_float4(olo[h].x, olo[h].y, ohi[h].x, ohi[h].y);
        *reinterpret_cast<float4*>(&Ored[w][h][d0]) = ov;
    }
    __syncthreads();

    // cross-warp sum + write partials (thread -> (head, d-chunk))
    {
        const int h  = w;
        const int dd = ln * 4;
        float4 acc = make_float4(0.f, 0.f, 0.f, 0.f);
        #pragma unroll
        for (int w2 = 0; w2 < 4; w2++) {
            const float4 ov = *reinterpret_cast<const float4*>(&Ored[w2][h][dd]);
            acc.x += ov.x; acc.y += ov.y; acc.z += ov.z; acc.w += ov.w;
        }
        *reinterpret_cast<float4*>(
            &g_po[(((size_t)n * KVH + kvh) * Gq + h) * Dd + dd]) = acc;
    }
    if (tid < Gq) {
        const size_t idx = ((size_t)n * KVH + kvh) * Gq + tid;
        g_pm[idx] = sm_m[tid];
        g_pl[idx] = sm_l[tid];
    }
}

// Merge the 14 block-partials per (batch, kvh) with flash-decoding rescale.
__global__ __launch_bounds__(128)
void attn_combine_kernel(const int* __restrict__ block_groups,
                         float* __restrict__ out)
{
    __shared__ unsigned char flag[NB];
    __shared__ short         list[NB];
    __shared__ float         coef[NB][Gq];
    __shared__ int           s_cnt;

    const int b   = blockIdx.x;
    const int kvh = blockIdx.y;
    const int tid = threadIdx.x;

    #pragma unroll
    for (int j = 0; j < (NB + 127) / 128; j++) {
        const int nn = tid + j * 128;
        if (nn < NB) flag[nn] = (block_groups[nn] == b) ? 1 : 0;
    }
    __syncthreads();
    if (tid == 0) {   // ordered compaction -> deterministic summation order
        int c = 0;
        for (int nn = 0; nn < NB; nn++)
            if (flag[nn]) list[c++] = (short)nn;
        s_cnt = c;
    }
    __syncthreads();
    const int cnt = s_cnt;

    if (tid < Gq) {
        const int h = tid;
        float M = -1.0e30f;
        for (int i = 0; i < cnt; i++) {
            const int nn = list[i];
            M = fmaxf(M, g_pm[((size_t)nn * KVH + kvh) * Gq + h]);
        }
        float den = 0.f;
        for (int i = 0; i < cnt; i++) {
            const int nn = list[i];
            const size_t idx = ((size_t)nn * KVH + kvh) * Gq + h;
            const float e = __expf(g_pm[idx] - M);
            coef[i][h] = e;
            den += g_pl[idx] * e;
        }
        const float inv = 1.f / den;
        for (int i = 0; i < cnt; i++) coef[i][h] *= inv;
    }
    __syncthreads();

    const int h  = tid >> 5;
    const int d0 = (tid & 31) * 4;
    float4 acc = make_float4(0.f, 0.f, 0.f, 0.f);
    for (int i = 0; i < cnt; i++) {
        const int nn = list[i];
        const float c = coef[i][h];
        const float4 ov = *reinterpret_cast<const float4*>(
            &g_po[(((size_t)nn * KVH + kvh) * Gq + h) * Dd + d0]);
        acc.x += c * ov.x; acc.y += c * ov.y; acc.z += c * ov.z; acc.w += c * ov.w;
    }
    *reinterpret_cast<float4*>(
        &out[(size_t)b * Hh * Dd + (size_t)(kvh * Gq + h) * Dd + d0]) = acc;
}

extern "C" void kernel_launch(void* const* d_in, const int* in_sizes, int n_in,
                              void* d_out, int out_size)
{
    const float* query         = (const float*)d_in[0];
    const float* key           = (const float*)d_in[1];
    const float* value         = (const float*)d_in[2];
    const float* key_cache     = (const float*)d_in[3];
    const float* value_cache   = (const float*)d_in[4];
    const int*   block_list    = (const int*)d_in[5];
    const int*   block_groups  = (const int*)d_in[6];
    /* d_in[7] block_mapping: one-hot, implied by block_groups */
    const float* block_bias    = (const float*)d_in[8];
    const int*   block_indices = (const int*)d_in[9];
    const int*   block_offsets = (const int*)d_in[10];
    const float* alibi_blocks  = (const float*)d_in[11];
    const float* alibi_slopes  = (const float*)d_in[12];

    attn_partial_kernel<<<dim3(NB, KVH), 128>>>(
        query, key, value, key_cache, value_cache,
        block_list, block_groups, block_bias,
        block_indices, block_offsets, alibi_blocks, alibi_slopes);

    attn_combine_kernel<<<dim3(Bq, KVH), 128>>>(
        block_groups, (float*)d_out);
}

// round 2
// speedup vs baseline: 1.3888x; 1.3888x over previous
#include <cuda_runtime.h>
#include <cstdint>

#define Bq 32
#define Hh 32
#define KVH 8
#define Gq 4
#define Dd 128
#define BS 128
#define NB 448
#define BPS 14                      /* blocks per sequence = NB/Bq */
#define SCALE 0.08838834764831845f

// Flash-decode partial scratch (static device globals: allocation-free).
__device__ float g_po[(size_t)NB * KVH * Gq * Dd];   // ~7.3 MB
__device__ float g_pm[NB * KVH * Gq];
__device__ float g_pl[NB * KVH * Gq];
__device__ int   g_cnt[Bq * KVH];                    // zero-init, reset after merge

// Packed f32x2 FMA (FFMA2) — 2 MACs per issue slot; only reachable via PTX.
__device__ __forceinline__ float2 ffma2(float2 a, float2 b, float2 c) {
    unsigned long long ua = *reinterpret_cast<unsigned long long*>(&a);
    unsigned long long ub = *reinterpret_cast<unsigned long long*>(&b);
    unsigned long long uc = *reinterpret_cast<unsigned long long*>(&c);
    unsigned long long ur;
    asm("fma.rn.f32x2 %0, %1, %2, %3;" : "=l"(ur) : "l"(ua), "l"(ub), "l"(uc));
    return *reinterpret_cast<float2*>(&ur);
}

__device__ __forceinline__ void prefetch_l2(const void* p) {
    asm volatile("prefetch.global.L2 [%0];" :: "l"(p));
}

__global__ __launch_bounds__(128, 4)
void attn_fused_kernel(
    const float* __restrict__ query,
    const float* __restrict__ knew,
    const float* __restrict__ vnew,
    const float* __restrict__ kcache,
    const float* __restrict__ vcache,
    const int*   __restrict__ block_list,
    const int*   __restrict__ block_groups,
    const float* __restrict__ block_bias,
    const int*   __restrict__ block_indices,
    const int*   __restrict__ block_offsets,
    const float* __restrict__ alibi_blocks,
    const float* __restrict__ slopes,
    float*       __restrict__ out)
{
    __shared__ float Ks[64][132];       // half K tile, padded rows (conflict-free LDS.128)
    __shared__ float Qs[Gq][Dd];        // scaled Q for the 4 grouped heads
    __shared__ float Sv[Gq][BS];        // scores -> p  (reused as merge coefs)
    __shared__ float Ored[4][Gq][Dd];   // per-warp PV partials
    __shared__ float sm_m[Gq], sm_l[Gq], sm_slope[Gq];
    __shared__ int   s_ins_slot, s_ins_b, s_last, s_cnt;
    __shared__ short s_list[BPS + 2];

    const int n   = blockIdx.x;
    const int kvh = blockIdx.y;
    const int tid = threadIdx.x;
    const int w   = tid >> 5;
    const int ln  = tid & 31;

    const int b    = block_groups[n];
    const int cblk = block_list[n];

    // validity of own token (masked tail of last block has bias = -1e9)
    const float bb_t    = block_bias[n * BS + tid];
    const float ab_t    = alibi_blocks[n * BS + tid];
    const int   valid_t = bb_t > -1.0e8f;

    // -------- front-load DRAM: prefetch entire K+V tile to L2 --------
    const size_t rowbase = (((size_t)cblk * BS + tid) * KVH + kvh) * Dd;
    if (valid_t) {
        const float* kr = kcache + rowbase;
        const float* vr = vcache + rowbase;
        prefetch_l2(kr);       prefetch_l2(kr + 32);
        prefetch_l2(kr + 64);  prefetch_l2(kr + 96);
        prefetch_l2(vr);       prefetch_l2(vr + 32);
        prefetch_l2(vr + 64);  prefetch_l2(vr + 96);
    }

    // decode-token insertion slot for this cache block?
    if (tid == 0) s_ins_slot = -1;
    if (tid < Gq) sm_slope[tid] = slopes[kvh * Gq + tid];
    const int nvalid = __syncthreads_count(valid_t);   // barrier + count
    if (tid < Bq) {
        if (block_indices[tid] == cblk) { s_ins_slot = block_offsets[tid]; s_ins_b = tid; }
    }

    // stage pre-scaled Q: 4 heads x 128 d
    {
        const int d0 = ln * 4;
        float4 q4 = *reinterpret_cast<const float4*>(
            query + (size_t)b * Hh * Dd + (size_t)(kvh * Gq + w) * Dd + d0);
        q4.x *= SCALE; q4.y *= SCALE; q4.z *= SCALE; q4.w *= SCALE;
        *reinterpret_cast<float4*>(&Qs[w][d0]) = q4;
    }
    __syncthreads();
    const int ins_slot = s_ins_slot;
    const int ins_b    = s_ins_b;

    // ---------------- QK: two 64-token halves through smem ----------------
    float2 accA[Gq], accB[Gq];
    #pragma unroll
    for (int h = 0; h < Gq; h++) { accA[h] = make_float2(0.f, 0.f); accB[h] = make_float2(0.f, 0.f); }

    #pragma unroll
    for (int hp = 0; hp < 2; hp++) {
        const int tbase = hp * 64;
        #pragma unroll
        for (int j = 0; j < 16; j++) {
            const int i   = tid + j * 128;
            const int tok = i >> 5;
            const int c   = i & 31;
            const int tg  = tbase + tok;
            if (tg < nvalid) {
                const float* src =
                    (tg == ins_slot)
                      ? (knew + ((size_t)ins_b * KVH + kvh) * Dd + c * 4)
                      : (kcache + (((size_t)cblk * BS + tg) * KVH + kvh) * Dd + c * 4);
                *reinterpret_cast<float4*>(&Ks[tok][c * 4]) =
                    *reinterpret_cast<const float4*>(src);
            }
        }
        __syncthreads();
        if ((tid >> 6) == hp && valid_t) {
            const int r = tid & 63;
            const float* krow = &Ks[r][0];
            #pragma unroll
            for (int c = 0; c < 32; c++) {
                const float4 k4 = *reinterpret_cast<const float4*>(krow + c * 4);
                const float2 klo = make_float2(k4.x, k4.y);
                const float2 khi = make_float2(k4.z, k4.w);
                #pragma unroll
                for (int h = 0; h < Gq; h++) {
                    const float4 q4 = *reinterpret_cast<const float4*>(&Qs[h][c * 4]);
                    accA[h] = ffma2(klo, make_float2(q4.x, q4.y), accA[h]);
                    accB[h] = ffma2(khi, make_float2(q4.z, q4.w), accB[h]);
                }
            }
        }
        __syncthreads();
    }

    // scores + alibi + bias
    float s[Gq];
    #pragma unroll
    for (int h = 0; h < Gq; h++) {
        s[h] = valid_t ? (accA[h].x + accA[h].y + accB[h].x + accB[h].y
                          + ab_t * sm_slope[h] + bb_t)
                       : -1.0e30f;
        Sv[h][tid] = s[h];
    }
    __syncthreads();

    // per-head block max (warp w owns head w)
    {
        float v = fmaxf(fmaxf(Sv[w][ln], Sv[w][ln + 32]),
                        fmaxf(Sv[w][ln + 64], Sv[w][ln + 96]));
        #pragma unroll
        for (int off = 16; off > 0; off >>= 1)
            v = fmaxf(v, __shfl_xor_sync(0xffffffffu, v, off));
        if (ln == 0) sm_m[w] = v;
    }
    __syncthreads();

    // p = exp(s - m_block); exactly 0 on masked tokens
    #pragma unroll
    for (int h = 0; h < Gq; h++) {
        const float p = valid_t ? __expf(s[h] - sm_m[h]) : 0.f;
        Sv[h][tid] = p;
    }
    __syncthreads();

    // per-head block sum
    {
        float v = Sv[w][ln] + Sv[w][ln + 32] + Sv[w][ln + 64] + Sv[w][ln + 96];
        #pragma unroll
        for (int off = 16; off > 0; off >>= 1)
            v += __shfl_xor_sync(0xffffffffu, v, off);
        if (ln == 0) sm_l[w] = v;
    }

    // ---------------- PV: warp w -> 32 tokens, lane owns 4 d's ----------------
    float2 olo[Gq], ohi[Gq];
    #pragma unroll
    for (int h = 0; h < Gq; h++) { olo[h] = make_float2(0.f, 0.f); ohi[h] = make_float2(0.f, 0.f); }
    const int d0 = ln * 4;

    if (w * 32 < nvalid) {
        const float* vbase = vcache + (((size_t)cblk * BS + w * 32) * KVH + kvh) * Dd + d0;
        #pragma unroll 2
        for (int i4 = 0; i4 < 8; i4++) {
            const int t0 = w * 32 + i4 * 4;
            float4 p4[Gq];
            #pragma unroll
            for (int h = 0; h < Gq; h++)
                p4[h] = *reinterpret_cast<const float4*>(&Sv[h][t0]);
            #pragma unroll
            for (int j = 0; j < 4; j++) {
                if (t0 + j < nvalid) {
                    const float4 v4 = *reinterpret_cast<const float4*>(
                        vbase + (size_t)(i4 * 4 + j) * KVH * Dd);
                    const float2 vlo = make_float2(v4.x, v4.y);
                    const float2 vhi = make_float2(v4.z, v4.w);
                    #pragma unroll
                    for (int h = 0; h < Gq; h++) {
                        const float pb = (j == 0) ? p4[h].x : (j == 1) ? p4[h].y
                                        : (j == 2) ? p4[h].z : p4[h].w;
                        const float2 pp = make_float2(pb, pb);
                        olo[h] = ffma2(pp, vlo, olo[h]);
                        ohi[h] = ffma2(pp, vhi, ohi[h]);
                    }
                }
            }
        }
        // exact decode-token correction: o += p_ins * (v_new - v_cache_old)
        if (ins_slot >= (w * 32) && ins_slot < (w * 32 + 32)) {
            const float4 vo = *reinterpret_cast<const float4*>(
                vcache + (((size_t)cblk * BS + ins_slot) * KVH + kvh) * Dd + d0);
            const float4 vn = *reinterpret_cast<const float4*>(
                vnew + ((size_t)ins_b * KVH + kvh) * Dd + d0);
            const float2 dlo = make_float2(vn.x - vo.x, vn.y - vo.y);
            const float2 dhi = make_float2(vn.z - vo.z, vn.w - vo.w);
            #pragma unroll
            for (int h = 0; h < Gq; h++) {
                const float pb = Sv[h][ins_slot];
                const float2 pp = make_float2(pb, pb);
                olo[h] = ffma2(pp, dlo, olo[h]);
                ohi[h] = ffma2(pp, dhi, ohi[h]);
            }
        }
    }

    #pragma unroll
    for (int h = 0; h < Gq; h++)
        *reinterpret_cast<float4*>(&Ored[w][h][d0]) =
            make_float4(olo[h].x, olo[h].y, ohi[h].x, ohi[h].y);
    __syncthreads();

    // cross-warp sum + write partials
    {
        const float4 o0 = *reinterpret_cast<const float4*>(&Ored[0][w][d0]);
        const float4 o1 = *reinterpret_cast<const float4*>(&Ored[1][w][d0]);
        const float4 o2 = *reinterpret_cast<const float4*>(&Ored[2][w][d0]);
        const float4 o3 = *reinterpret_cast<const float4*>(&Ored[3][w][d0]);
        const float4 acc = make_float4(o0.x + o1.x + o2.x + o3.x,
                                       o0.y + o1.y + o2.y + o3.y,
                                       o0.z + o1.z + o2.z + o3.z,
                                       o0.w + o1.w + o2.w + o3.w);
        *reinterpret_cast<float4*>(
            &g_po[(((size_t)n * KVH + kvh) * Gq + w) * Dd + d0]) = acc;
    }
    if (tid < Gq) {
        const size_t idx = ((size_t)n * KVH + kvh) * Gq + tid;
        g_pm[idx] = sm_m[tid];
        g_pl[idx] = sm_l[tid];
    }

    // ---------------- fused merge: last CTA of (b, kvh) group ----------------
    __threadfence();
    __syncthreads();
    if (tid == 0)
        s_last = (atomicAdd(&g_cnt[b * KVH + kvh], 1) == (BPS - 1));
    __syncthreads();
    if (!s_last) return;

    // deterministic ordered group list (block_groups is small + hot in L2)
    if (tid == 0) {
        int c = 0;
        for (int nn = 0; nn < NB && c < BPS; nn++)
            if (block_groups[nn] == b) s_list[c++] = (short)nn;
        s_cnt = c;
    }
    __syncthreads();
    const int cnt = s_cnt;

    if (tid < Gq) {                      // rescale coefs (reuse Sv as coef[h][i])
        const int h = tid;
        float M = -1.0e30f;
        for (int i = 0; i < cnt; i++)
            M = fmaxf(M, g_pm[((size_t)s_list[i] * KVH + kvh) * Gq + h]);
        float den = 0.f;
        for (int i = 0; i < cnt; i++) {
            const size_t idx = ((size_t)s_list[i] * KVH + kvh) * Gq + h;
            const float e = __expf(g_pm[idx] - M);
            Sv[h][i] = e;
            den += g_pl[idx] * e;
        }
        const float inv = 1.f / den;
        for (int i = 0; i < cnt; i++) Sv[h][i] *= inv;
    }
    __syncthreads();

    {
        float4 acc = make_float4(0.f, 0.f, 0.f, 0.f);
        for (int i = 0; i < cnt; i++) {
            const float c = Sv[w][i];
            const float4 ov = *reinterpret_cast<const float4*>(
                &g_po[(((size_t)s_list[i] * KVH + kvh) * Gq + w) * Dd + d0]);
            acc.x += c * ov.x; acc.y += c * ov.y; acc.z += c * ov.z; acc.w += c * ov.w;
        }
        *reinterpret_cast<float4*>(
            &out[(size_t)b * Hh * Dd + (size_t)(kvh * Gq + w) * Dd + d0]) = acc;
    }
    if (tid == 0) g_cnt[b * KVH + kvh] = 0;   // reset for next replay
}

extern "C" void kernel_launch(void* const* d_in, const int* in_sizes, int n_in,
                              void* d_out, int out_size)
{
    const float* query         = (const float*)d_in[0];
    const float* key           = (const float*)d_in[1];
    const float* value         = (const float*)d_in[2];
    const float* key_cache     = (const float*)d_in[3];
    const float* value_cache   = (const float*)d_in[4];
    const int*   block_list    = (const int*)d_in[5];
    const int*   block_groups  = (const int*)d_in[6];
    /* d_in[7] block_mapping: one-hot, implied by block_groups */
    const float* block_bias    = (const float*)d_in[8];
    const int*   block_indices = (const int*)d_in[9];
    const int*   block_offsets = (const int*)d_in[10];
    const float* alibi_blocks  = (const float*)d_in[11];
    const float* alibi_slopes  = (const float*)d_in[12];

    attn_fused_kernel<<<dim3(NB, KVH), 128>>>(
        query, key, value, key_cache, value_cache,
        block_list, block_groups, block_bias,
        block_indices, block_offsets, alibi_blocks, alibi_slopes,
        (float*)d_out);
}

// round 3
// speedup vs baseline: 1.6024x; 1.1538x over previous
#include <cuda_runtime.h>
#include <cstdint>

#define Bq 32
#define Hh 32
#define KVH 8
#define Gq 4
#define Dd 128
#define BS 128
#define NB 448
#define BPS 14                      /* blocks per sequence = NB/Bq */
#define SCALE 0.08838834764831845f
#define KSTR 144                    /* Ks row stride (floats): 144%32==16 -> conflict-free quads */
#define SVS  136                    /* Sv row stride (floats): 136*4B 16B-aligned rows */

// Flash-decode partial scratch (static device globals: allocation-free).
__device__ float g_po[(size_t)NB * KVH * Gq * Dd];   // ~7.3 MB
__device__ float g_pm[NB * KVH * Gq];
__device__ float g_pl[NB * KVH * Gq];
__device__ int   g_cnt[Bq * KVH];                    // zero-init, reset after merge

// Packed f32x2 FMA (FFMA2) — 2 MACs per issue slot; only reachable via PTX.
__device__ __forceinline__ float2 ffma2(float2 a, float2 b, float2 c) {
    unsigned long long ua = *reinterpret_cast<unsigned long long*>(&a);
    unsigned long long ub = *reinterpret_cast<unsigned long long*>(&b);
    unsigned long long uc = *reinterpret_cast<unsigned long long*>(&c);
    unsigned long long ur;
    asm("fma.rn.f32x2 %0, %1, %2, %3;" : "=l"(ur) : "l"(ua), "l"(ub), "l"(uc));
    return *reinterpret_cast<float2*>(&ur);
}

__device__ __forceinline__ void prefetch_l2(const void* p) {
    asm volatile("prefetch.global.L2 [%0];" :: "l"(p));
}

__global__ __launch_bounds__(128, 6)
void attn_fused_kernel(
    const float* __restrict__ query,
    const float* __restrict__ knew,
    const float* __restrict__ vnew,
    const float* __restrict__ kcache,
    const float* __restrict__ vcache,
    const int*   __restrict__ block_list,
    const int*   __restrict__ block_groups,
    const float* __restrict__ block_bias,
    const int*   __restrict__ block_indices,
    const int*   __restrict__ block_offsets,
    const float* __restrict__ alibi_blocks,
    const float* __restrict__ slopes,
    float*       __restrict__ out)
{
    __shared__ float Ks[32][KSTR];      // 18.4 KB K stage (32 tokens)
    __shared__ float Qs[Gq][Dd];        // 2 KB scaled Q
    __shared__ float Sv[Gq][SVS];       // 2.2 KB scores -> p -> merge coefs
    __shared__ float Ored[4][Gq][Dd];   // 8 KB per-warp PV partials
    __shared__ float wmax[4][Gq];
    __shared__ float psum[4][Gq];
    __shared__ int   s_ins_slot, s_ins_b, s_last, s_cnt;
    __shared__ short s_list[BPS + 2];

    const int n   = blockIdx.x;
    const int kvh = blockIdx.y;
    const int tid = threadIdx.x;
    const int w   = tid >> 5;
    const int ln  = tid & 31;

    const int b    = block_groups[n];
    const int cblk = block_list[n];

    // validity of own token (masked tail of last block has bias = -1e9)
    const float bb_t    = block_bias[n * BS + tid];
    const float ab_t    = alibi_blocks[n * BS + tid];
    const int   valid_t = bb_t > -1.0e8f;

    // front-load DRAM: prefetch whole K+V tile into L2
    const size_t rowbase = (((size_t)cblk * BS + tid) * KVH + kvh) * Dd;
    if (valid_t) {
        const float* kr = kcache + rowbase;
        const float* vr = vcache + rowbase;
        prefetch_l2(kr);       prefetch_l2(kr + 32);
        prefetch_l2(kr + 64);  prefetch_l2(kr + 96);
        prefetch_l2(vr);       prefetch_l2(vr + 32);
        prefetch_l2(vr + 64);  prefetch_l2(vr + 96);
    }

    if (tid == 0) s_ins_slot = -1;
    if (tid < Bq && block_indices[tid] == cblk) {
        s_ins_slot = block_offsets[tid];
        s_ins_b    = tid;
    }

    // stage pre-scaled Q (warp w -> head w)
    {
        const int dq = ln * 4;
        float4 q4 = *reinterpret_cast<const float4*>(
            query + (size_t)b * Hh * Dd + (size_t)(kvh * Gq + w) * Dd + dq);
        q4.x *= SCALE; q4.y *= SCALE; q4.z *= SCALE; q4.w *= SCALE;
        *reinterpret_cast<float4*>(&Qs[w][dq]) = q4;
    }
    const float sl0 = slopes[kvh * Gq + 0];
    const float sl1 = slopes[kvh * Gq + 1];
    const float sl2 = slopes[kvh * Gq + 2];
    const float sl3 = slopes[kvh * Gq + 3];

    const int nvalid = __syncthreads_count(valid_t);   // barrier + count
    const int ins_slot = s_ins_slot;
    const int ins_b    = s_ins_b;

    // ---------------- QK: four 32-token stages, all threads compute ----------------
    // thread -> (row = tid>>2, quarter = tid&3): 32 d's each, quad shfl-reduce.
    const int qrt  = tid & 3;
    const int rloc = tid >> 2;      // 0..31 (lane quads aligned within warp)

    #pragma unroll
    for (int st = 0; st < 4; st++) {
        const int sbase = st * 32;
        if (st) __syncthreads();    // WAR: previous compute done before overwrite
        #pragma unroll
        for (int j = 0; j < 8; j++) {
            const int i   = tid + j * 128;
            const int row = i >> 5;
            const int cc  = i & 31;
            const int tg  = sbase + row;
            if (tg < nvalid) {
                const float* src =
                    (tg == ins_slot)
                      ? (knew + ((size_t)ins_b * KVH + kvh) * Dd + cc * 4)
                      : (kcache + (((size_t)cblk * BS + tg) * KVH + kvh) * Dd + cc * 4);
                *reinterpret_cast<float4*>(&Ks[row][cc * 4]) =
                    *reinterpret_cast<const float4*>(src);
            }
        }
        __syncthreads();

        float2 acc[Gq];
        #pragma unroll
        for (int h = 0; h < Gq; h++) acc[h] = make_float2(0.f, 0.f);
        #pragma unroll
        for (int j = 0; j < 8; j++) {
            const int c4 = (qrt + 4 * j) * 4;         // interleaved quarter chunks
            const float4 k4 = *reinterpret_cast<const float4*>(&Ks[rloc][c4]);
            const float2 klo = make_float2(k4.x, k4.y);
            const float2 khi = make_float2(k4.z, k4.w);
            #pragma unroll
            for (int h = 0; h < Gq; h++) {
                const float4 q4 = *reinterpret_cast<const float4*>(&Qs[h][c4]);
                acc[h] = ffma2(klo, make_float2(q4.x, q4.y), acc[h]);
                acc[h] = ffma2(khi, make_float2(q4.z, q4.w), acc[h]);
            }
        }
        // quad reduction (lanes qrt 0..3 share a token)
        float v0 = acc[0].x + acc[0].y;
        float v1 = acc[1].x + acc[1].y;
        float v2 = acc[2].x + acc[2].y;
        float v3 = acc[3].x + acc[3].y;
        v0 += __shfl_xor_sync(0xffffffffu, v0, 1);
        v1 += __shfl_xor_sync(0xffffffffu, v1, 1);
        v2 += __shfl_xor_sync(0xffffffffu, v2, 1);
        v3 += __shfl_xor_sync(0xffffffffu, v3, 1);
        v0 += __shfl_xor_sync(0xffffffffu, v0, 2);
        v1 += __shfl_xor_sync(0xffffffffu, v1, 2);
        v2 += __shfl_xor_sync(0xffffffffu, v2, 2);
        v3 += __shfl_xor_sync(0xffffffffu, v3, 2);
        const float dv = (qrt == 0) ? v0 : (qrt == 1) ? v1 : (qrt == 2) ? v2 : v3;
        Sv[qrt][sbase + rloc] = dv;   // lane qrt writes head qrt for its token
    }
    __syncthreads();

    // ---------------- softmax ----------------
    float s0, s1, s2, s3;
    if (valid_t) {
        s0 = Sv[0][tid] + ab_t * sl0 + bb_t;
        s1 = Sv[1][tid] + ab_t * sl1 + bb_t;
        s2 = Sv[2][tid] + ab_t * sl2 + bb_t;
        s3 = Sv[3][tid] + ab_t * sl3 + bb_t;
    } else {
        s0 = s1 = s2 = s3 = -1.0e30f;
    }
    {
        float m0 = s0, m1 = s1, m2 = s2, m3 = s3;
        #pragma unroll
        for (int off = 16; off > 0; off >>= 1) {
            m0 = fmaxf(m0, __shfl_xor_sync(0xffffffffu, m0, off));
            m1 = fmaxf(m1, __shfl_xor_sync(0xffffffffu, m1, off));
            m2 = fmaxf(m2, __shfl_xor_sync(0xffffffffu, m2, off));
            m3 = fmaxf(m3, __shfl_xor_sync(0xffffffffu, m3, off));
        }
        if (ln == 0) { wmax[w][0] = m0; wmax[w][1] = m1; wmax[w][2] = m2; wmax[w][3] = m3; }
    }
    __syncthreads();
    const float m0 = fmaxf(fmaxf(wmax[0][0], wmax[1][0]), fmaxf(wmax[2][0], wmax[3][0]));
    const float m1 = fmaxf(fmaxf(wmax[0][1], wmax[1][1]), fmaxf(wmax[2][1], wmax[3][1]));
    const float m2 = fmaxf(fmaxf(wmax[0][2], wmax[1][2]), fmaxf(wmax[2][2], wmax[3][2]));
    const float m3 = fmaxf(fmaxf(wmax[0][3], wmax[1][3]), fmaxf(wmax[2][3], wmax[3][3]));

    const float p0 = valid_t ? __expf(s0 - m0) : 0.f;
    const float p1 = valid_t ? __expf(s1 - m1) : 0.f;
    const float p2 = valid_t ? __expf(s2 - m2) : 0.f;
    const float p3 = valid_t ? __expf(s3 - m3) : 0.f;
    Sv[0][tid] = p0; Sv[1][tid] = p1; Sv[2][tid] = p2; Sv[3][tid] = p3;
    {
        float t0 = p0, t1 = p1, t2 = p2, t3 = p3;
        #pragma unroll
        for (int off = 16; off > 0; off >>= 1) {
            t0 += __shfl_xor_sync(0xffffffffu, t0, off);
            t1 += __shfl_xor_sync(0xffffffffu, t1, off);
            t2 += __shfl_xor_sync(0xffffffffu, t2, off);
            t3 += __shfl_xor_sync(0xffffffffu, t3, off);
        }
        if (ln == 0) { psum[w][0] = t0; psum[w][1] = t1; psum[w][2] = t2; psum[w][3] = t3; }
    }
    __syncthreads();

    // ---------------- PV: warp w -> 32 tokens, lane owns 4 d's ----------------
    float2 olo[Gq], ohi[Gq];
    #pragma unroll
    for (int h = 0; h < Gq; h++) { olo[h] = make_float2(0.f, 0.f); ohi[h] = make_float2(0.f, 0.f); }
    const int d0 = ln * 4;

    if (w * 32 < nvalid) {
        const float* vbase = vcache + (((size_t)cblk * BS + w * 32) * KVH + kvh) * Dd + d0;
        #pragma unroll 2
        for (int i4 = 0; i4 < 8; i4++) {
            const int t0 = w * 32 + i4 * 4;
            float4 p4[Gq];
            #pragma unroll
            for (int h = 0; h < Gq; h++)
                p4[h] = *reinterpret_cast<const float4*>(&Sv[h][t0]);
            #pragma unroll
            for (int j = 0; j < 4; j++) {
                if (t0 + j < nvalid) {
                    const float4 v4 = *reinterpret_cast<const float4*>(
                        vbase + (size_t)(i4 * 4 + j) * KVH * Dd);
                    const float2 vlo = make_float2(v4.x, v4.y);
                    const float2 vhi = make_float2(v4.z, v4.w);
                    #pragma unroll
                    for (int h = 0; h < Gq; h++) {
                        const float pb = (j == 0) ? p4[h].x : (j == 1) ? p4[h].y
                                        : (j == 2) ? p4[h].z : p4[h].w;
                        const float2 pp = make_float2(pb, pb);
                        olo[h] = ffma2(pp, vlo, olo[h]);
                        ohi[h] = ffma2(pp, vhi, ohi[h]);
                    }
                }
            }
        }
        // exact decode-token correction: o += p_ins * (v_new - v_cache_old)
        if (ins_slot >= (w * 32) && ins_slot < (w * 32 + 32)) {
            const float4 vo = *reinterpret_cast<const float4*>(
                vcache + (((size_t)cblk * BS + ins_slot) * KVH + kvh) * Dd + d0);
            const float4 vn = *reinterpret_cast<const float4*>(
                vnew + ((size_t)ins_b * KVH + kvh) * Dd + d0);
            const float2 dlo = make_float2(vn.x - vo.x, vn.y - vo.y);
            const float2 dhi = make_float2(vn.z - vo.z, vn.w - vo.w);
            #pragma unroll
            for (int h = 0; h < Gq; h++) {
                const float pb = Sv[h][ins_slot];
                const float2 pp = make_float2(pb, pb);
                olo[h] = ffma2(pp, dlo, olo[h]);
                ohi[h] = ffma2(pp, dhi, ohi[h]);
            }
        }
    }

    #pragma unroll
    for (int h = 0; h < Gq; h++)
        *reinterpret_cast<float4*>(&Ored[w][h][d0]) =
            make_float4(olo[h].x, olo[h].y, ohi[h].x, ohi[h].y);
    __syncthreads();

    // cross-warp sum + write partials (warp w -> head w, lane -> d chunk)
    {
        const float4 o0 = *reinterpret_cast<const float4*>(&Ored[0][w][d0]);
        const float4 o1 = *reinterpret_cast<const float4*>(&Ored[1][w][d0]);
        const float4 o2 = *reinterpret_cast<const float4*>(&Ored[2][w][d0]);
        const float4 o3 = *reinterpret_cast<const float4*>(&Ored[3][w][d0]);
        const float4 acc = make_float4(o0.x + o1.x + o2.x + o3.x,
                                       o0.y + o1.y + o2.y + o3.y,
                                       o0.z + o1.z + o2.z + o3.z,
                                       o0.w + o1.w + o2.w + o3.w);
        *reinterpret_cast<float4*>(
            &g_po[(((size_t)n * KVH + kvh) * Gq + w) * Dd + d0]) = acc;
    }
    if (tid < Gq) {
        const size_t idx = ((size_t)n * KVH + kvh) * Gq + tid;
        g_pm[idx] = (tid == 0) ? m0 : (tid == 1) ? m1 : (tid == 2) ? m2 : m3;
        g_pl[idx] = psum[0][tid] + psum[1][tid] + psum[2][tid] + psum[3][tid];
    }

    // ---------------- fused merge: last CTA of (b, kvh) group ----------------
    __threadfence();
    __syncthreads();
    if (tid == 0)
        s_last = (atomicAdd(&g_cnt[b * KVH + kvh], 1) == (BPS - 1));
    __syncthreads();
    if (!s_last) return;

    // parallel flag fill (alias Ks as scratch), ordered compaction from smem
    unsigned char* flag = reinterpret_cast<unsigned char*>(&Ks[0][0]);
    #pragma unroll
    for (int j = 0; j < (NB + 127) / 128; j++) {
        const int nn = tid + j * 128;
        if (nn < NB) flag[nn] = (block_groups[nn] == b) ? 1 : 0;
    }
    __syncthreads();
    if (tid == 0) {
        int c = 0;
        for (int nn = 0; nn < NB && c < BPS; nn++)
            if (flag[nn]) s_list[c++] = (short)nn;
        s_cnt = c;
    }
    __syncthreads();
    const int cnt = s_cnt;

    if (tid < Gq) {                    // rescale coefs (reuse Sv rows)
        const int h = tid;
        float M = -1.0e30f;
        for (int i = 0; i < cnt; i++)
            M = fmaxf(M, g_pm[((size_t)s_list[i] * KVH + kvh) * Gq + h]);
        float den = 0.f;
        for (int i = 0; i < cnt; i++) {
            const size_t idx = ((size_t)s_list[i] * KVH + kvh) * Gq + h;
            const float e = __expf(g_pm[idx] - M);
            Sv[h][i] = e;
            den += g_pl[idx] * e;
        }
        const float inv = 1.f / den;
        for (int i = 0; i < cnt; i++) Sv[h][i] *= inv;
    }
    __syncthreads();

    {
        float4 acc = make_float4(0.f, 0.f, 0.f, 0.f);
        for (int i = 0; i < cnt; i++) {
            const float c = Sv[w][i];
            const float4 ov = *reinterpret_cast<const float4*>(
                &g_po[(((size_t)s_list[i] * KVH + kvh) * Gq + w) * Dd + d0]);
            acc.x += c * ov.x; acc.y += c * ov.y; acc.z += c * ov.z; acc.w += c * ov.w;
        }
        *reinterpret_cast<float4*>(
            &out[(size_t)b * Hh * Dd + (size_t)(kvh * Gq + w) * Dd + d0]) = acc;
    }
    if (tid == 0) g_cnt[b * KVH + kvh] = 0;   // reset for next replay
}

extern "C" void kernel_launch(void* const* d_in, const int* in_sizes, int n_in,
                              void* d_out, int out_size)
{
    const float* query         = (const float*)d_in[0];
    const float* key           = (const float*)d_in[1];
    const float* value         = (const float*)d_in[2];
    const float* key_cache     = (const float*)d_in[3];
    const float* value_cache   = (const float*)d_in[4];
    const int*   block_list    = (const int*)d_in[5];
    const int*   block_groups  = (const int*)d_in[6];
    /* d_in[7] block_mapping: one-hot, implied by block_groups */
    const float* block_bias    = (const float*)d_in[8];
    const int*   block_indices = (const int*)d_in[9];
    const int*   block_offsets = (const int*)d_in[10];
    const float* alibi_blocks  = (const float*)d_in[11];
    const float* alibi_slopes  = (const float*)d_in[12];

    attn_fused_kernel<<<dim3(NB, KVH), 128>>>(
        query, key, value, key_cache, value_cache,
        block_list, block_groups, block_bias,
        block_indices, block_offsets, alibi_blocks, alibi_slopes,
        (float*)d_out);
}

// round 4
// speedup vs baseline: 1.7959x; 1.1208x over previous
#include <cuda_runtime.h>
#include <cstdint>

#define Bq 32
#define Hh 32
#define KVH 8
#define Gq 4
#define Dd 128
#define BS 128
#define NB 448
#define BPS 14                      /* blocks per sequence = NB/Bq */
#define SCALE 0.08838834764831845f
#define SVS  132                    /* Sv row stride: 132*4B rows stay 16B-aligned */

// Flash-decode partial scratch (static device globals: allocation-free).
__device__ float g_po[(size_t)NB * KVH * Gq * Dd];   // ~7.3 MB
__device__ float g_pm[NB * KVH * Gq];
__device__ float g_pl[NB * KVH * Gq];
__device__ int   g_cnt[Bq * KVH];                    // zero-init, reset after merge

// Packed f32x2 FMA (FFMA2) — 2 MACs per issue slot; only reachable via PTX.
__device__ __forceinline__ float2 ffma2(float2 a, float2 b, float2 c) {
    unsigned long long ua = *reinterpret_cast<unsigned long long*>(&a);
    unsigned long long ub = *reinterpret_cast<unsigned long long*>(&b);
    unsigned long long uc = *reinterpret_cast<unsigned long long*>(&c);
    unsigned long long ur;
    asm("fma.rn.f32x2 %0, %1, %2, %3;" : "=l"(ur) : "l"(ua), "l"(ub), "l"(uc));
    return *reinterpret_cast<float2*>(&ur);
}

__device__ __forceinline__ void prefetch_l2(const void* p) {
    asm volatile("prefetch.global.L2 [%0];" :: "l"(p));
}

__global__ __launch_bounds__(128, 8)
void attn_fused_kernel(
    const float* __restrict__ query,
    const float* __restrict__ knew,
    const float* __restrict__ vnew,
    const float* __restrict__ kcache,
    const float* __restrict__ vcache,
    const int*   __restrict__ block_list,
    const int*   __restrict__ block_groups,
    const float* __restrict__ block_bias,
    const int*   __restrict__ block_indices,
    const int*   __restrict__ block_offsets,
    const float* __restrict__ alibi_blocks,
    const float* __restrict__ slopes,
    float*       __restrict__ out)
{
    __shared__ float Qs[Gq][Dd];        // 2 KB scaled Q
    __shared__ float Sv[Gq][SVS];       // 2.1 KB p values -> merge coefs
    __shared__ float Ored[4][Gq][Dd];   // 8 KB per-warp PV partials (merge scratch too)
    __shared__ float wmax[4][Gq];
    __shared__ float psum[4][Gq];
    __shared__ int   s_last, s_cnt;
    __shared__ short s_list[BPS + 2];

    const int n   = blockIdx.x;
    const int kvh = blockIdx.y;
    const int tid = threadIdx.x;
    const int w   = tid >> 5;
    const int ln  = tid & 31;

    const int b    = block_groups[n];
    const int cblk = block_list[n];

    // validity of own token (masked tail of last block has bias = -1e9)
    const float bb_t    = block_bias[n * BS + tid];
    const float ab_t    = alibi_blocks[n * BS + tid];
    const int   valid_t = bb_t > -1.0e8f;

    // decode-token insertion: warp-uniform ballot, race-free, no smem
    int ins_slot = -1, ins_b = 0;
    {
        const unsigned mask =
            __ballot_sync(0xffffffffu, block_indices[ln] == cblk);
        if (mask) {
            ins_b    = __ffs(mask) - 1;
            ins_slot = block_offsets[ins_b];
        }
    }

    // prefetch V tile into L2 (used in PV phase -> genuine overlap with QK)
    const size_t rowbase = (((size_t)cblk * BS + tid) * KVH + kvh) * Dd;
    if (valid_t) {
        const float* vr = vcache + rowbase;
        prefetch_l2(vr);       prefetch_l2(vr + 32);
        prefetch_l2(vr + 64);  prefetch_l2(vr + 96);
    }

    // stage pre-scaled Q (warp w -> head w)
    {
        const int dq = ln * 4;
        float4 q4 = *reinterpret_cast<const float4*>(
            query + (size_t)b * Hh * Dd + (size_t)(kvh * Gq + w) * Dd + dq);
        q4.x *= SCALE; q4.y *= SCALE; q4.z *= SCALE; q4.w *= SCALE;
        *reinterpret_cast<float4*>(&Qs[w][dq]) = q4;
    }
    const float sl0 = slopes[kvh * Gq + 0];
    const float sl1 = slopes[kvh * Gq + 1];
    const float sl2 = slopes[kvh * Gq + 2];
    const float sl3 = slopes[kvh * Gq + 3];

    const int nvalid = __syncthreads_count(valid_t);   // barrier + count

    // ---------------- QK: thread owns token tid, K streamed from global ----------------
    float2 acc[Gq];
    #pragma unroll
    for (int h = 0; h < Gq; h++) acc[h] = make_float2(0.f, 0.f);

    if (valid_t) {
        const float* krow =
            (tid == ins_slot)
              ? (knew + ((size_t)ins_b * KVH + kvh) * Dd)
              : (kcache + rowbase);
        #pragma unroll
        for (int cb = 0; cb < 4; cb++) {
            float4 kb[8];                         // 8 LDG.128 in flight
            #pragma unroll
            for (int j = 0; j < 8; j++)
                kb[j] = *reinterpret_cast<const float4*>(krow + (cb * 8 + j) * 4);
            #pragma unroll
            for (int j = 0; j < 8; j++) {
                const int c4 = (cb * 8 + j) * 4;
                const float2 klo = make_float2(kb[j].x, kb[j].y);
                const float2 khi = make_float2(kb[j].z, kb[j].w);
                #pragma unroll
                for (int h = 0; h < Gq; h++) {
                    const float4 q4 = *reinterpret_cast<const float4*>(&Qs[h][c4]);
                    acc[h] = ffma2(klo, make_float2(q4.x, q4.y), acc[h]);
                    acc[h] = ffma2(khi, make_float2(q4.z, q4.w), acc[h]);
                }
            }
        }
    }

    // ---------------- softmax (scores live in-register) ----------------
    float s0, s1, s2, s3;
    if (valid_t) {
        s0 = acc[0].x + acc[0].y + ab_t * sl0 + bb_t;
        s1 = acc[1].x + acc[1].y + ab_t * sl1 + bb_t;
        s2 = acc[2].x + acc[2].y + ab_t * sl2 + bb_t;
        s3 = acc[3].x + acc[3].y + ab_t * sl3 + bb_t;
    } else {
        s0 = s1 = s2 = s3 = -1.0e30f;
    }
    {
        float m0 = s0, m1 = s1, m2 = s2, m3 = s3;
        #pragma unroll
        for (int off = 16; off > 0; off >>= 1) {
            m0 = fmaxf(m0, __shfl_xor_sync(0xffffffffu, m0, off));
            m1 = fmaxf(m1, __shfl_xor_sync(0xffffffffu, m1, off));
            m2 = fmaxf(m2, __shfl_xor_sync(0xffffffffu, m2, off));
            m3 = fmaxf(m3, __shfl_xor_sync(0xffffffffu, m3, off));
        }
        if (ln == 0) { wmax[w][0] = m0; wmax[w][1] = m1; wmax[w][2] = m2; wmax[w][3] = m3; }
    }
    __syncthreads();
    const float m0 = fmaxf(fmaxf(wmax[0][0], wmax[1][0]), fmaxf(wmax[2][0], wmax[3][0]));
    const float m1 = fmaxf(fmaxf(wmax[0][1], wmax[1][1]), fmaxf(wmax[2][1], wmax[3][1]));
    const float m2 = fmaxf(fmaxf(wmax[0][2], wmax[1][2]), fmaxf(wmax[2][2], wmax[3][2]));
    const float m3 = fmaxf(fmaxf(wmax[0][3], wmax[1][3]), fmaxf(wmax[2][3], wmax[3][3]));

    const float p0 = valid_t ? __expf(s0 - m0) : 0.f;
    const float p1 = valid_t ? __expf(s1 - m1) : 0.f;
    const float p2 = valid_t ? __expf(s2 - m2) : 0.f;
    const float p3 = valid_t ? __expf(s3 - m3) : 0.f;
    Sv[0][tid] = p0; Sv[1][tid] = p1; Sv[2][tid] = p2; Sv[3][tid] = p3;
    {
        float t0 = p0, t1 = p1, t2 = p2, t3 = p3;
        #pragma unroll
        for (int off = 16; off > 0; off >>= 1) {
            t0 += __shfl_xor_sync(0xffffffffu, t0, off);
            t1 += __shfl_xor_sync(0xffffffffu, t1, off);
            t2 += __shfl_xor_sync(0xffffffffu, t2, off);
            t3 += __shfl_xor_sync(0xffffffffu, t3, off);
        }
        if (ln == 0) { psum[w][0] = t0; psum[w][1] = t1; psum[w][2] = t2; psum[w][3] = t3; }
    }
    __syncthreads();

    // ---------------- PV: warp w -> 32 tokens, lane owns 4 d's ----------------
    float2 olo[Gq], ohi[Gq];
    #pragma unroll
    for (int h = 0; h < Gq; h++) { olo[h] = make_float2(0.f, 0.f); ohi[h] = make_float2(0.f, 0.f); }
    const int d0 = ln * 4;

    if (w * 32 < nvalid) {
        const float* vbase = vcache + (((size_t)cblk * BS + w * 32) * KVH + kvh) * Dd + d0;
        #pragma unroll 2
        for (int i4 = 0; i4 < 8; i4++) {
            const int t0 = w * 32 + i4 * 4;
            float4 p4[Gq];
            #pragma unroll
            for (int h = 0; h < Gq; h++)
                p4[h] = *reinterpret_cast<const float4*>(&Sv[h][t0]);
            #pragma unroll
            for (int j = 0; j < 4; j++) {
                if (t0 + j < nvalid) {
                    const float4 v4 = *reinterpret_cast<const float4*>(
                        vbase + (size_t)(i4 * 4 + j) * KVH * Dd);
                    const float2 vlo = make_float2(v4.x, v4.y);
                    const float2 vhi = make_float2(v4.z, v4.w);
                    #pragma unroll
                    for (int h = 0; h < Gq; h++) {
                        const float pb = (j == 0) ? p4[h].x : (j == 1) ? p4[h].y
                                        : (j == 2) ? p4[h].z : p4[h].w;
                        const float2 pp = make_float2(pb, pb);
                        olo[h] = ffma2(pp, vlo, olo[h]);
                        ohi[h] = ffma2(pp, vhi, ohi[h]);
                    }
                }
            }
        }
        // exact decode-token correction: o += p_ins * (v_new - v_cache_old)
        if (ins_slot >= (w * 32) && ins_slot < (w * 32 + 32)) {
            const float4 vo = *reinterpret_cast<const float4*>(
                vcache + (((size_t)cblk * BS + ins_slot) * KVH + kvh) * Dd + d0);
            const float4 vn = *reinterpret_cast<const float4*>(
                vnew + ((size_t)ins_b * KVH + kvh) * Dd + d0);
            const float2 dlo = make_float2(vn.x - vo.x, vn.y - vo.y);
            const float2 dhi = make_float2(vn.z - vo.z, vn.w - vo.w);
            #pragma unroll
            for (int h = 0; h < Gq; h++) {
                const float pb = Sv[h][ins_slot];
                const float2 pp = make_float2(pb, pb);
                olo[h] = ffma2(pp, dlo, olo[h]);
                ohi[h] = ffma2(pp, dhi, ohi[h]);
            }
        }
    }

    #pragma unroll
    for (int h = 0; h < Gq; h++)
        *reinterpret_cast<float4*>(&Ored[w][h][d0]) =
            make_float4(olo[h].x, olo[h].y, ohi[h].x, ohi[h].y);
    __syncthreads();

    // cross-warp sum + write partials (warp w -> head w, lane -> d chunk)
    {
        const float4 o0 = *reinterpret_cast<const float4*>(&Ored[0][w][d0]);
        const float4 o1 = *reinterpret_cast<const float4*>(&Ored[1][w][d0]);
        const float4 o2 = *reinterpret_cast<const float4*>(&Ored[2][w][d0]);
        const float4 o3 = *reinterpret_cast<const float4*>(&Ored[3][w][d0]);
        const float4 acc4 = make_float4(o0.x + o1.x + o2.x + o3.x,
                                        o0.y + o1.y + o2.y + o3.y,
                                        o0.z + o1.z + o2.z + o3.z,
                                        o0.w + o1.w + o2.w + o3.w);
        *reinterpret_cast<float4*>(
            &g_po[(((size_t)n * KVH + kvh) * Gq + w) * Dd + d0]) = acc4;
    }
    if (tid < Gq) {
        const size_t idx = ((size_t)n * KVH + kvh) * Gq + tid;
        g_pm[idx] = (tid == 0) ? m0 : (tid == 1) ? m1 : (tid == 2) ? m2 : m3;
        g_pl[idx] = psum[0][tid] + psum[1][tid] + psum[2][tid] + psum[3][tid];
    }

    // ---------------- fused merge: last CTA of (b, kvh) group ----------------
    __threadfence();
    __syncthreads();
    if (tid == 0)
        s_last = (atomicAdd(&g_cnt[b * KVH + kvh], 1) == (BPS - 1));
    __syncthreads();
    if (!s_last) return;

    // parallel flag fill (alias Ored as scratch), ordered compaction
    unsigned char* flag = reinterpret_cast<unsigned char*>(&Ored[0][0][0]);
    #pragma unroll
    for (int j = 0; j < (NB + 127) / 128; j++) {
        const int nn = tid + j * 128;
        if (nn < NB) flag[nn] = (block_groups[nn] == b) ? 1 : 0;
    }
    __syncthreads();
    if (tid == 0) {
        int c = 0;
        for (int nn = 0; nn < NB && c < BPS; nn++)
            if (flag[nn]) s_list[c++] = (short)nn;
        s_cnt = c;
    }
    __syncthreads();
    const int cnt = s_cnt;

    if (tid < Gq) {                    // rescale coefs (reuse Sv rows)
        const int h = tid;
        float M = -1.0e30f;
        for (int i = 0; i < cnt; i++)
            M = fmaxf(M, g_pm[((size_t)s_list[i] * KVH + kvh) * Gq + h]);
        float den = 0.f;
        for (int i = 0; i < cnt; i++) {
            const size_t idx = ((size_t)s_list[i] * KVH + kvh) * Gq + h;
            const float e = __expf(g_pm[idx] - M);
            Sv[h][i] = e;
            den += g_pl[idx] * e;
        }
        const float inv = 1.f / den;
        for (int i = 0; i < cnt; i++) Sv[h][i] *= inv;
    }
    __syncthreads();

    {
        float4 acc4 = make_float4(0.f, 0.f, 0.f, 0.f);
        for (int i = 0; i < cnt; i++) {
            const float c = Sv[w][i];
            const float4 ov = *reinterpret_cast<const float4*>(
                &g_po[(((size_t)s_list[i] * KVH + kvh) * Gq + w) * Dd + d0]);
            acc4.x += c * ov.x; acc4.y += c * ov.y;
            acc4.z += c * ov.z; acc4.w += c * ov.w;
        }
        *reinterpret_cast<float4*>(
            &out[(size_t)b * Hh * Dd + (size_t)(kvh * Gq + w) * Dd + d0]) = acc4;
    }
    if (tid == 0) g_cnt[b * KVH + kvh] = 0;   // reset for next replay
}

extern "C" void kernel_launch(void* const* d_in, const int* in_sizes, int n_in,
                              void* d_out, int out_size)
{
    const float* query         = (const float*)d_in[0];
    const float* key           = (const float*)d_in[1];
    const float* value         = (const float*)d_in[2];
    const float* key_cache     = (const float*)d_in[3];
    const float* value_cache   = (const float*)d_in[4];
    const int*   block_list    = (const int*)d_in[5];
    const int*   block_groups  = (const int*)d_in[6];
    /* d_in[7] block_mapping: one-hot, implied by block_groups */
    const float* block_bias    = (const float*)d_in[8];
    const int*   block_indices = (const int*)d_in[9];
    const int*   block_offsets = (const int*)d_in[10];
    const float* alibi_blocks  = (const float*)d_in[11];
    const float* alibi_slopes  = (const float*)d_in[12];

    attn_fused_kernel<<<dim3(NB, KVH), 128>>>(
        query, key, value, key_cache, value_cache,
        block_list, block_groups, block_bias,
        block_indices, block_offsets, alibi_blocks, alibi_slopes,
        (float*)d_out);
}